// round 6
// baseline (speedup 1.0000x reference)
#include <cuda_runtime.h>
#include <math.h>
#include <float.h>

#define Bsz 2
#define Mdim 2048
#define Ndim 2048
#define Kk 32
#define Gg 60
#define TMRB 8         // m-rows per block in k1 (4 warps x 2 rows)
#define TN 256         // n per tile in k1

__device__ int   g_nn[Bsz * Mdim];
__device__ float g_qs[Bsz * Mdim * 32];
__device__ float g_kt[Bsz * Ndim * 32];
__device__ float g_vt[Bsz * Ndim * 32];
__device__ float g_x [Bsz * Mdim * 32];
__device__ float g_attn[Bsz * 32 * Mdim];
__device__ float g_h[Bsz * 64 * Mdim];
__device__ float g_mean[Bsz * 64];
__device__ float g_istd[Bsz * 64];

__device__ __forceinline__ unsigned ordf(float f) {
    unsigned u = __float_as_uint(f);
    return (u & 0x80000000u) ? ~u : (u | 0x80000000u);
}

__device__ __forceinline__ void ins8(float v, int n, float tv[8], int ti[8]) {
    if (v <= tv[7]) return;
    if (v > tv[3]) {
        if (v > tv[1]) {
            if (v > tv[0]) {
                tv[7]=tv[6];ti[7]=ti[6]; tv[6]=tv[5];ti[6]=ti[5]; tv[5]=tv[4];ti[5]=ti[4];
                tv[4]=tv[3];ti[4]=ti[3]; tv[3]=tv[2];ti[3]=ti[2]; tv[2]=tv[1];ti[2]=ti[1];
                tv[1]=tv[0];ti[1]=ti[0]; tv[0]=v; ti[0]=n;
            } else {
                tv[7]=tv[6];ti[7]=ti[6]; tv[6]=tv[5];ti[6]=ti[5]; tv[5]=tv[4];ti[5]=ti[4];
                tv[4]=tv[3];ti[4]=ti[3]; tv[3]=tv[2];ti[3]=ti[2]; tv[2]=tv[1];ti[2]=ti[1];
                tv[1]=v; ti[1]=n;
            }
        } else {
            if (v > tv[2]) {
                tv[7]=tv[6];ti[7]=ti[6]; tv[6]=tv[5];ti[6]=ti[5]; tv[5]=tv[4];ti[5]=ti[4];
                tv[4]=tv[3];ti[4]=ti[3]; tv[3]=tv[2];ti[3]=ti[2]; tv[2]=v; ti[2]=n;
            } else {
                tv[7]=tv[6];ti[7]=ti[6]; tv[6]=tv[5];ti[6]=ti[5]; tv[5]=tv[4];ti[5]=ti[4];
                tv[4]=tv[3];ti[4]=ti[3]; tv[3]=v; ti[3]=n;
            }
        }
    } else {
        if (v > tv[5]) {
            if (v > tv[4]) {
                tv[7]=tv[6];ti[7]=ti[6]; tv[6]=tv[5];ti[6]=ti[5]; tv[5]=tv[4];ti[5]=ti[4];
                tv[4]=v; ti[4]=n;
            } else {
                tv[7]=tv[6];ti[7]=ti[6]; tv[6]=tv[5];ti[6]=ti[5]; tv[5]=v; ti[5]=n;
            }
        } else {
            if (v > tv[6]) { tv[7]=tv[6];ti[7]=ti[6]; tv[6]=v; ti[6]=n; }
            else { tv[7]=v; ti[7]=n; }
        }
    }
}

// ========== k0: per-point projections ==========
__global__ __launch_bounds__(256) void k0_proj(const float* __restrict__ src, const float* __restrict__ tgt,
    const float* __restrict__ wq, const float* __restrict__ bq,
    const float* __restrict__ wk, const float* __restrict__ bk,
    const float* __restrict__ wv, const float* __restrict__ bv,
    int dual, int blkoff)
{
    __shared__ float sw1[1024], sw2[1024], sb1[32], sb2[32];
    const int tid = threadIdx.x;
    const float* in = dual ? tgt : src;
    const float* W1 = dual ? wk : wq;  const float* B1 = dual ? bk : bq;
    for (int i = tid; i < 1024; i += 256) { sw1[i] = W1[i]; if (dual) sw2[i] = wv[i]; }
    if (tid < 32) { sb1[tid] = B1[tid]; if (dual) sb2[tid] = bv[tid]; }
    __syncthreads();
    const int half = tid >> 7;
    const int p = (blockIdx.x + blkoff) * 128 + (tid & 127);
    const int b = p >> 11, pl = p & 2047;
    float* o1 = dual ? g_kt : g_qs;
    float a1[16], a2[16];
#pragma unroll
    for (int o = 0; o < 16; o++) { a1[o] = sb1[half*16+o]; a2[o] = dual ? sb2[half*16+o] : 0.f; }
#pragma unroll
    for (int i = 0; i < 32; i++) {
        float xv = in[((size_t)(b*32+i))*2048 + pl];
#pragma unroll
        for (int o = 0; o < 16; o++) {
            a1[o] += sw1[(half*16+o)*32+i] * xv;
            if (dual) a2[o] += sw2[(half*16+o)*32+i] * xv;
        }
    }
#pragma unroll
    for (int o = 0; o < 16; o++) {
        o1[(size_t)p*32 + half*16+o] = a1[o];
        if (dual) g_vt[(size_t)p*32 + half*16+o] = a2[o];
    }
}

// ========== k1: selection (register top-8) + fused attention for one row ==========
__device__ __forceinline__ void sel_attn8(float tv[8], int ti[8],
    int lane, int b, size_t bm, size_t bn,
    const float* __restrict__ s_srcrow, float* __restrict__ scratch,
    int* __restrict__ outl, const float* __restrict__ tgt)
{
    int nvalid = 8, nbr = 0;
    for (int it = 0; it < Kk; it++) {
        unsigned mykey = ordf(tv[0]);
        unsigned bu = __reduce_max_sync(0xffffffffu, mykey);
        int cand = (mykey == bu) ? ti[0] : 0x7fffffff;
        int bi = __reduce_min_sync(0xffffffffu, cand);
        if (lane == it) nbr = bi;
        if (lane == 0) outl[it] = bi;
        if (it == 0 && lane == 0) g_nn[bm] = bi;
        if (ti[0] == bi) {
            tv[0]=tv[1];ti[0]=ti[1]; tv[1]=tv[2];ti[1]=ti[2]; tv[2]=tv[3];ti[2]=ti[3];
            tv[3]=tv[4];ti[3]=ti[4]; tv[4]=tv[5];ti[4]=ti[5]; tv[5]=tv[6];ti[5]=ti[6];
            tv[6]=tv[7];ti[6]=ti[7]; tv[7]=-FLT_MAX; ti[7]=0x7fffffff;
            if (--nvalid == 0) {
                // cold path: rebuild top-8 for this lane from global (bit-identical chain)
#pragma unroll 1
                for (int t = 0; t < Ndim/TN; t++) {
#pragma unroll 1
                    for (int hf = 0; hf < 2; hf++) {
#pragma unroll 1
                        for (int j = 0; j < 4; j++) {
                            int n = t*TN + hf*128 + lane*4 + j;
                            bool used = (n == bi);
                            for (int q = 0; q < it; q++) used |= (outl[q] == n);
                            if (used) continue;
                            float sc = 0.f;
#pragma unroll
                            for (int d = 0; d < 32; d++)
                                sc += s_srcrow[d] * tgt[((size_t)(b*32+d))*(size_t)Ndim + n];
                            ins8(sc, n, tv, ti);
                        }
                    }
                }
                nvalid = 8;
            }
        }
    }

    // fused attention: lane = k-index, neighbor = nbr
    const float4* q4  = (const float4*)(g_qs + bm*32);
    const float4* kk4 = (const float4*)(g_kt + (bn + nbr)*32);
    float s0=0,s1=0,s2=0,s3=0;
#pragma unroll
    for (int c = 0; c < 8; c++) {
        float4 qv = q4[c], kv = kk4[c];
        s0 += qv.x*kv.x; s1 += qv.y*kv.y; s2 += qv.z*kv.z; s3 += qv.w*kv.w;
    }
    const float sf = 0.35355339059327373f;   // 1/sqrt(8)
    s0*=sf; s1*=sf; s2*=sf; s3*=sf;
    float m0=s0,m1=s1,m2=s2,m3=s3;
#pragma unroll
    for (int o = 16; o; o >>= 1) {
        m0=fmaxf(m0,__shfl_xor_sync(0xffffffffu,m0,o));
        m1=fmaxf(m1,__shfl_xor_sync(0xffffffffu,m1,o));
        m2=fmaxf(m2,__shfl_xor_sync(0xffffffffu,m2,o));
        m3=fmaxf(m3,__shfl_xor_sync(0xffffffffu,m3,o));
    }
    float e0=expf(s0-m0), e1=expf(s1-m1), e2=expf(s2-m2), e3=expf(s3-m3);
    float z0=e0,z1=e1,z2=e2,z3=e3;
#pragma unroll
    for (int o = 16; o; o >>= 1) {
        z0+=__shfl_xor_sync(0xffffffffu,z0,o); z1+=__shfl_xor_sync(0xffffffffu,z1,o);
        z2+=__shfl_xor_sync(0xffffffffu,z2,o); z3+=__shfl_xor_sync(0xffffffffu,z3,o);
    }
    const float p0=e0/z0, p1=e1/z1, p2=e2/z2, p3=e3/z3;

    float* sT = scratch;          // 32*33 floats
    float* sP = scratch + 1056;   // 128 floats
    const float4* vv4 = (const float4*)(g_vt + (bn + nbr)*32);
#pragma unroll
    for (int c = 0; c < 8; c++) {
        float4 vv = vv4[c];
        sT[(4*c+0)*33 + lane] = vv.x;
        sT[(4*c+1)*33 + lane] = vv.y;
        sT[(4*c+2)*33 + lane] = vv.z;
        sT[(4*c+3)*33 + lane] = vv.w;
    }
    ((float4*)sP)[lane] = make_float4(p0, p1, p2, p3);
    __syncwarp();
    float acc = 0.f;
    const int r = lane & 3;
#pragma unroll
    for (int k = 0; k < 32; k++)
        acc += sP[k*4 + r] * sT[lane*33 + k];
    g_x[bm*32 + lane] = acc;
}

// ========== k1: score GEMM (2 rows/warp, no score smem) + top-K + attention ==========
__global__ __launch_bounds__(128, 4) void k1_fused(const float* __restrict__ src,
                                                   const float* __restrict__ tgt)
{
    extern __shared__ float sm[];
    float* s_src = sm;            // 8 rows * 32 = 256 floats
    float* s_B   = sm + 256;      // 8192 floats: tile, later scratch+outlist
    const int tid = threadIdx.x, b = blockIdx.y, w = tid >> 5, lane = tid & 31;
    const int m0 = blockIdx.x * TMRB;
    const size_t bn = (size_t)b * Ndim;

    for (int i = tid; i < TMRB*32; i += 128) {
        int row = i >> 5, d = i & 31;
        s_src[i] = src[((size_t)(b*32+d))*Mdim + m0 + row];
    }
    __syncthreads();

    float tvA[8], tvB[8]; int tiA[8], tiB[8];
#pragma unroll
    for (int q = 0; q < 8; q++) {
        tvA[q] = -FLT_MAX; tvB[q] = -FLT_MAX;
        tiA[q] = 0x7fffffff; tiB[q] = 0x7fffffff;
    }
    const float* sA = s_src + (w*2)*32;
    const float* sB = sA + 32;
    const float4* gt = (const float4*)(tgt + ((size_t)b*32)*Ndim);
    float4* tile4 = (float4*)s_B;

    for (int t = 0; t < Ndim/TN; t++) {
        const int n0 = t * TN;
#pragma unroll
        for (int kk = 0; kk < 16; kk++) {
            int i = tid + kk*128;          // 2048 float4 slots
            int d = i >> 6, c = i & 63;
            tile4[i] = gt[(size_t)d*(Ndim/4) + (n0>>2) + c];
        }
        __syncthreads();
        float4 aA0 = make_float4(0,0,0,0), aA1 = make_float4(0,0,0,0);
        float4 aB0 = make_float4(0,0,0,0), aB1 = make_float4(0,0,0,0);
#pragma unroll
        for (int d = 0; d < 32; d++) {
            float a = sA[d], bb = sB[d];
            float4 t0 = tile4[d*64 + lane];
            float4 t1 = tile4[d*64 + 32 + lane];
            aA0.x += a*t0.x; aA0.y += a*t0.y; aA0.z += a*t0.z; aA0.w += a*t0.w;
            aA1.x += a*t1.x; aA1.y += a*t1.y; aA1.z += a*t1.z; aA1.w += a*t1.w;
            aB0.x += bb*t0.x; aB0.y += bb*t0.y; aB0.z += bb*t0.z; aB0.w += bb*t0.w;
            aB1.x += bb*t1.x; aB1.y += bb*t1.y; aB1.z += bb*t1.z; aB1.w += bb*t1.w;
        }
        const int nb0 = n0 + lane*4, nb1 = n0 + 128 + lane*4;
        ins8(aA0.x,nb0,tvA,tiA); ins8(aA0.y,nb0+1,tvA,tiA); ins8(aA0.z,nb0+2,tvA,tiA); ins8(aA0.w,nb0+3,tvA,tiA);
        ins8(aA1.x,nb1,tvA,tiA); ins8(aA1.y,nb1+1,tvA,tiA); ins8(aA1.z,nb1+2,tvA,tiA); ins8(aA1.w,nb1+3,tvA,tiA);
        ins8(aB0.x,nb0,tvB,tiB); ins8(aB0.y,nb0+1,tvB,tiB); ins8(aB0.z,nb0+2,tvB,tiB); ins8(aB0.w,nb0+3,tvB,tiB);
        ins8(aB1.x,nb1,tvB,tiB); ins8(aB1.y,nb1+1,tvB,tiB); ins8(aB1.z,nb1+2,tvB,tiB); ins8(aB1.w,nb1+3,tvB,tiB);
        __syncthreads();
    }

    float* scratch = s_B + w*1184;
    int*   outl    = (int*)(s_B + 4*1184) + w*32;
    const int mA = m0 + w*2;
    sel_attn8(tvA, tiA, lane, b, (size_t)b*Mdim + mA,     bn, sA, scratch, outl, tgt);
    sel_attn8(tvB, tiB, lane, b, (size_t)b*Mdim + mA + 1, bn, sB, scratch, outl, tgt);
}

// ========== k2b: wm + w1 (GEMM over m) ==========
__global__ __launch_bounds__(128) void k2b_mlp(const float* __restrict__ finv, const float* __restrict__ srcf,
    const float* __restrict__ wm, const float* __restrict__ bm_,
    const float* __restrict__ w1, const float* __restrict__ b1_)
{
    __shared__ float s_wm[1024], s_w1[6144], s_bm[32], s_b1[64];
    __shared__ float s_x[32*33], s_attn[32*33];
    const int b = blockIdx.y, tid = threadIdx.x, m0 = blockIdx.x * 32;
    const int lane = tid & 31, og = tid >> 5, m = m0 + lane;

    for (int i = tid; i < 6144; i += 128) s_w1[i] = w1[i];
    for (int i = tid; i < 1024; i += 128) s_wm[i] = wm[i];
    if (tid < 64) s_b1[tid] = b1_[tid];
    if (tid < 32) s_bm[tid] = bm_[tid];
    for (int i = tid; i < 1024; i += 128) {
        int ml = i >> 5, d = i & 31;
        s_x[ml*33+d] = g_x[(((size_t)b*Mdim + m0) << 5) + i];
    }
    __syncthreads();
    float a[8];
#pragma unroll
    for (int j = 0; j < 8; j++) a[j] = s_bm[og*8+j];
#pragma unroll
    for (int i = 0; i < 32; i++) {
        float xv = s_x[lane*33+i];
#pragma unroll
        for (int j = 0; j < 8; j++) a[j] += s_wm[(og*8+j)*32+i] * xv;
    }
#pragma unroll
    for (int j = 0; j < 8; j++) {
        int o = og*8+j;
        s_attn[lane*33+o] = a[j];
        g_attn[((size_t)(b*32+o))*Mdim + m] = a[j];
    }
    __syncthreads();
    float h[16];
#pragma unroll
    for (int j = 0; j < 16; j++) h[j] = s_b1[og*16+j];
#pragma unroll
    for (int i = 0; i < 32; i++) {
        float xv = finv[((size_t)(b*32+i))*Mdim + m];
#pragma unroll
        for (int j = 0; j < 16; j++) h[j] += s_w1[(og*16+j)*96+i] * xv;
    }
#pragma unroll
    for (int i = 0; i < 32; i++) {
        float xv = srcf[((size_t)(b*32+i))*Mdim + m];
#pragma unroll
        for (int j = 0; j < 16; j++) h[j] += s_w1[(og*16+j)*96+32+i] * xv;
    }
#pragma unroll
    for (int i = 0; i < 32; i++) {
        float xv = s_attn[lane*33+i];
#pragma unroll
        for (int j = 0; j < 16; j++) h[j] += s_w1[(og*16+j)*96+64+i] * xv;
    }
#pragma unroll
    for (int j = 0; j < 16; j++)
        g_h[((size_t)(b*64 + og*16+j))*Mdim + m] = h[j];
}

// ========== k3: instance-norm stats ==========
__global__ void k3_stats()
{
    const int bc = blockIdx.x;
    const float4* row4 = (const float4*)(g_h + (size_t)bc * Mdim);
    float s = 0.f, s2 = 0.f;
    for (int i = threadIdx.x; i < Mdim/4; i += blockDim.x) {
        float4 v = row4[i];
        s  += v.x + v.y + v.z + v.w;
        s2 += v.x*v.x + v.y*v.y + v.z*v.z + v.w*v.w;
    }
    __shared__ float rs[32], rs2[32];
#pragma unroll
    for (int o = 16; o; o >>= 1) {
        s += __shfl_xor_sync(0xffffffffu, s, o);
        s2 += __shfl_xor_sync(0xffffffffu, s2, o);
    }
    if ((threadIdx.x & 31) == 0) { rs[threadIdx.x>>5] = s; rs2[threadIdx.x>>5] = s2; }
    __syncthreads();
    if (threadIdx.x == 0) {
        float S = 0, S2 = 0;
        for (int i = 0; i < (int)(blockDim.x>>5); i++) { S += rs[i]; S2 += rs2[i]; }
        float mu = S / (float)Mdim;
        float var = S2 / (float)Mdim - mu*mu;
        g_mean[bc] = mu; g_istd[bc] = rsqrtf(var + 1e-5f);
    }
}

// ========== k4: norm + relu + w2/wres (GEMM over m) ==========
__global__ __launch_bounds__(128) void k4_out(const float* __restrict__ finv, const float* __restrict__ srcf,
    const float* __restrict__ w2, const float* __restrict__ b2_,
    const float* __restrict__ wres, const float* __restrict__ bres, float* __restrict__ out)
{
    __shared__ float s_w[32*160], s_in[160*33], s_b[32];
    const int b = blockIdx.y, tid = threadIdx.x, m0 = blockIdx.x * 32;
    const int lane = tid & 31, og = tid >> 5;

    for (int i = tid; i < 5120; i += 128) {
        int o = i / 160, c = i % 160;
        s_w[i] = (c < 64) ? w2[o*64+c] : wres[o*96 + (c-64)];
    }
    if (tid < 32) s_b[tid] = b2_[tid] + bres[tid];
    for (int i = tid; i < 2048; i += 128) {
        int c = i >> 5, ml = i & 31;
        int bc = b*64 + c;
        float v = (g_h[(size_t)bc*Mdim + m0+ml] - g_mean[bc]) * g_istd[bc];
        s_in[c*33+ml] = fmaxf(v, 0.f);
    }
    for (int i = tid; i < 1024; i += 128) {
        int c = i >> 5, ml = i & 31;
        s_in[(64 +c)*33+ml] = finv[((size_t)(b*32+c))*Mdim + m0+ml];
        s_in[(96 +c)*33+ml] = srcf[((size_t)(b*32+c))*Mdim + m0+ml];
        s_in[(128+c)*33+ml] = g_attn[((size_t)(b*32+c))*Mdim + m0+ml];
    }
    __syncthreads();
    float acc[8];
#pragma unroll
    for (int j = 0; j < 8; j++) acc[j] = s_b[og*8+j];
    for (int c = 0; c < 160; c++) {
        float xv = s_in[c*33+lane];
#pragma unroll
        for (int j = 0; j < 8; j++) acc[j] += s_w[(og*8+j)*160+c] * xv;
    }
#pragma unroll
    for (int j = 0; j < 8; j++)
        out[((size_t)(b*32 + og*8+j))*Mdim + m0+lane] = acc[j];
}

// ========== k5: R_indicator via C-matrix ==========
__global__ __launch_bounds__(128) void k5_rind(const float* __restrict__ seqv, const float* __restrict__ teqv,
                                               const int* __restrict__ perms, float* __restrict__ out)
{
    __shared__ int   s_p[Gg*Gg];
    __shared__ float s_sr[Gg*8];      // [j][f]
    __shared__ float s_tk[Gg*12];     // [g][f] padded
    __shared__ float s_C[Gg*Gg];      // [j][g]
    __shared__ int s_nn;
    const int b = blockIdx.y, tid = threadIdx.x;
    for (int i = tid; i < Gg*Gg; i += 128) s_p[i] = perms[i];

    for (int rr = 0; rr < 8; rr++) {
        const int m = blockIdx.x * 8 + rr;
        __syncthreads();
        if (tid == 0) s_nn = g_nn[(size_t)b*Mdim + m];
        __syncthreads();
        const int nn = s_nn;
        for (int i = tid; i < Gg*8; i += 128) {
            int f = i / Gg, j = i % Gg;
            s_sr[j*8  + f] = seqv[(((size_t)(b*8+f))*Mdim + m )*Gg + j];
            s_tk[j*12 + f] = teqv[(((size_t)(b*8+f))*Ndim + nn)*Gg + j];
        }
        __syncthreads();
        const float4* sr4 = (const float4*)s_sr;
        for (int idx = tid; idx < Gg*Gg; idx += 128) {
            int j = idx / Gg, g = idx % Gg;
            float4 a0 = sr4[j*2], a1 = sr4[j*2+1];
            const float4* tg = (const float4*)(s_tk + g*12);
            float4 t0 = tg[0], t1 = tg[1];
            s_C[j*Gg + g] = a0.x*t0.x + a0.y*t0.y + a0.z*t0.z + a0.w*t0.w
                          + a1.x*t1.x + a1.y*t1.y + a1.z*t1.z + a1.w*t1.w;
        }
        __syncthreads();
        if (tid < Gg) {
            float acc = 0.f;
#pragma unroll 4
            for (int g = 0; g < Gg; g++)
                acc += s_C[s_p[g*Gg + tid]*Gg + g];
            out[(size_t)Bsz*32*Mdim + ((size_t)b*Gg + tid)*Mdim + m] = acc;
        }
    }
}

// ========== launch ==========
extern "C" void kernel_launch(void* const* d_in, const int* in_sizes, int n_in,
                              void* d_out, int out_size)
{
    (void)in_sizes; (void)n_in; (void)out_size;
    const float* src  = (const float*)d_in[0];
    const float* tgt  = (const float*)d_in[1];
    const float* seqv = (const float*)d_in[2];
    const float* teqv = (const float*)d_in[3];
    const float* finv = (const float*)d_in[4];
    const int*   perms = (const int*)d_in[5];
    const float* wq = (const float*)d_in[6];   const float* bq = (const float*)d_in[7];
    const float* wk = (const float*)d_in[8];   const float* bk = (const float*)d_in[9];
    const float* wv = (const float*)d_in[10];  const float* bv = (const float*)d_in[11];
    const float* wm = (const float*)d_in[12];  const float* bm = (const float*)d_in[13];
    const float* w1 = (const float*)d_in[14];  const float* b1 = (const float*)d_in[15];
    const float* w2 = (const float*)d_in[16];  const float* b2 = (const float*)d_in[17];
    const float* wres = (const float*)d_in[18]; const float* bres = (const float*)d_in[19];
    float* out = (float*)d_out;

    const int smem1 = (TMRB*32 + 8192) * 4;   // 33792 B

    // launches 1-3 (k1 stays launch #4 for ncu capture)
    k0_proj<<<16, 256>>>(src, tgt, wq, bq, wk, bk, wv, bv, 0, 0);
    k0_proj<<<16, 256>>>(src, tgt, wq, bq, wk, bk, wv, bv, 0, 16);
    k0_proj<<<32, 256>>>(src, tgt, wq, bq, wk, bk, wv, bv, 1, 0);
    k1_fused<<<dim3(Mdim/TMRB, Bsz), 128, smem1>>>(src, tgt);     // launch #4
    k2b_mlp<<<dim3(Mdim/32, Bsz), 128>>>(finv, src, wm, bm, w1, b1);
    k3_stats<<<128, 256>>>();
    k4_out<<<dim3(Mdim/32, Bsz), 128>>>(finv, src, w2, b2, wres, bres, out);
    k5_rind<<<dim3(Mdim/8, Bsz), 128>>>(seqv, teqv, perms, out);
}

// round 7
// speedup vs baseline: 1.1158x; 1.1158x over previous
#include <cuda_runtime.h>
#include <math.h>
#include <float.h>

#define Bsz 2
#define Mdim 2048
#define Ndim 2048
#define Kk 32
#define Gg 60
#define TMRB 8         // m-rows per block in k1 (4 warps x 2 rows)
#define TN 256         // n per tile in k1

__device__ int   g_nn[Bsz * Mdim];
__device__ float g_qs[Bsz * Mdim * 32];
__device__ float g_kt[Bsz * Ndim * 32];
__device__ float g_vt[Bsz * Ndim * 32];
__device__ float g_x [Bsz * Mdim * 32];
__device__ float g_attn[Bsz * 32 * Mdim];
__device__ float g_h[Bsz * 64 * Mdim];
__device__ float g_mean[Bsz * 64];
__device__ float g_istd[Bsz * 64];

__device__ __forceinline__ unsigned ordf(float f) {
    unsigned u = __float_as_uint(f);
    return (u & 0x80000000u) ? ~u : (u | 0x80000000u);
}
__device__ __forceinline__ void ins4(float v, int n, float tv[4], int ti[4]) {
    if (v > tv[3]) {
        if (v > tv[1]) {
            if (v > tv[0]) { tv[3]=tv[2];ti[3]=ti[2]; tv[2]=tv[1];ti[2]=ti[1]; tv[1]=tv[0];ti[1]=ti[0]; tv[0]=v;ti[0]=n; }
            else           { tv[3]=tv[2];ti[3]=ti[2]; tv[2]=tv[1];ti[2]=ti[1]; tv[1]=v;ti[1]=n; }
        } else if (v > tv[2]) { tv[3]=tv[2];ti[3]=ti[2]; tv[2]=v;ti[2]=n; }
        else { tv[3]=v; ti[3]=n; }
    }
}
// guarded group-insert: exact (skips only when every element would no-op)
__device__ __forceinline__ void gins4(float4 v, int nb, float tv[4], int ti[4]) {
    float mx = fmaxf(fmaxf(v.x, v.y), fmaxf(v.z, v.w));
    if (mx > tv[3]) {
        ins4(v.x, nb, tv, ti); ins4(v.y, nb+1, tv, ti);
        ins4(v.z, nb+2, tv, ti); ins4(v.w, nb+3, tv, ti);
    }
}

// ---- packed fp32x2 helpers (Blackwell) ----
__device__ __forceinline__ unsigned long long pk2(float x) {
    unsigned long long r;
    asm("mov.b64 %0, {%1, %1};" : "=l"(r) : "r"(__float_as_uint(x)));
    return r;
}
__device__ __forceinline__ unsigned long long fma2(unsigned long long a, unsigned long long b, unsigned long long c) {
    unsigned long long d;
    asm("fma.rn.f32x2 %0, %1, %2, %3;" : "=l"(d) : "l"(a), "l"(b), "l"(c));
    return d;
}
__device__ __forceinline__ float2 upk(unsigned long long v) {
    unsigned lo, hi;
    asm("mov.b64 {%0, %1}, %2;" : "=r"(lo), "=r"(hi) : "l"(v));
    return make_float2(__uint_as_float(lo), __uint_as_float(hi));
}

// ========== k0: per-point projections (z=0: Q from src; z=1: K,V from tgt) ==========
__global__ __launch_bounds__(256) void k0_proj(const float* __restrict__ src, const float* __restrict__ tgt,
    const float* __restrict__ wq, const float* __restrict__ bq,
    const float* __restrict__ wk, const float* __restrict__ bk,
    const float* __restrict__ wv, const float* __restrict__ bv)
{
    __shared__ float sw1[1024], sw2[1024], sb1[32], sb2[32];
    const int tid = threadIdx.x;
    const int dual = blockIdx.z;
    const float* in = dual ? tgt : src;
    const float* W1 = dual ? wk : wq;  const float* B1 = dual ? bk : bq;
    for (int i = tid; i < 1024; i += 256) { sw1[i] = W1[i]; if (dual) sw2[i] = wv[i]; }
    if (tid < 32) { sb1[tid] = B1[tid]; if (dual) sb2[tid] = bv[tid]; }
    __syncthreads();
    const int half = tid >> 7;
    const int p = blockIdx.x * 128 + (tid & 127);
    const int b = p >> 11, pl = p & 2047;
    float* o1 = dual ? g_kt : g_qs;
    float a1[16], a2[16];
#pragma unroll
    for (int o = 0; o < 16; o++) { a1[o] = sb1[half*16+o]; a2[o] = dual ? sb2[half*16+o] : 0.f; }
#pragma unroll
    for (int i = 0; i < 32; i++) {
        float xv = in[((size_t)(b*32+i))*2048 + pl];
#pragma unroll
        for (int o = 0; o < 16; o++) {
            a1[o] += sw1[(half*16+o)*32+i] * xv;
            if (dual) a2[o] += sw2[(half*16+o)*32+i] * xv;
        }
    }
#pragma unroll
    for (int o = 0; o < 16; o++) {
        o1[(size_t)p*32 + half*16+o] = a1[o];
        if (dual) g_vt[(size_t)p*32 + half*16+o] = a2[o];
    }
}

// ========== k1: selection + fused attention for one m-row (score smem version) ==========
__device__ __forceinline__ void sel_attn(float* ws, float4* ws4, int lane,
                                         float tv[4], int ti[4],
                                         size_t bm, size_t bn)
{
    int nvalid = 4;
    int nbr = 0;
    for (int it = 0; it < Kk; it++) {
        unsigned bu = __reduce_max_sync(0xffffffffu, ordf(tv[0]));
        int cand = (ordf(tv[0]) == bu) ? ti[0] : 0x7fffffff;
        int bi = __reduce_min_sync(0xffffffffu, cand);
        if (lane == it) nbr = bi;
        if (it == 0 && lane == 0) g_nn[bm] = bi;
        if (ti[0] == bi) {
            ws[bi] = -FLT_MAX;
            tv[0]=tv[1];ti[0]=ti[1]; tv[1]=tv[2];ti[1]=ti[2]; tv[2]=tv[3];ti[2]=ti[3];
            tv[3] = -FLT_MAX; ti[3] = 0x7fffffff;
            if (--nvalid == 0) {
#pragma unroll 4
                for (int t = 0; t < Ndim/TN; t++) {
                    float4 v0 = ws4[t*64 + lane];
                    float4 v1 = ws4[t*64 + 32 + lane];
                    int nb0 = t*TN + lane*4, nb1 = t*TN + 128 + lane*4;
                    ins4(v0.x,nb0,tv,ti); ins4(v0.y,nb0+1,tv,ti); ins4(v0.z,nb0+2,tv,ti); ins4(v0.w,nb0+3,tv,ti);
                    ins4(v1.x,nb1,tv,ti); ins4(v1.y,nb1+1,tv,ti); ins4(v1.z,nb1+2,tv,ti); ins4(v1.w,nb1+3,tv,ti);
                }
                nvalid = 4;
            }
        }
    }

    // fused attention: lane = k-index, neighbor = nbr
    const float4* q4  = (const float4*)(g_qs + bm*32);
    const float4* kk4 = (const float4*)(g_kt + (bn + nbr)*32);
    float s0=0,s1=0,s2=0,s3=0;
#pragma unroll
    for (int c = 0; c < 8; c++) {
        float4 qv = q4[c], kv = kk4[c];
        s0 += qv.x*kv.x; s1 += qv.y*kv.y; s2 += qv.z*kv.z; s3 += qv.w*kv.w;
    }
    const float sf = 0.35355339059327373f;   // 1/sqrt(8)
    s0*=sf; s1*=sf; s2*=sf; s3*=sf;
    float m0=s0,m1=s1,m2=s2,m3=s3;
#pragma unroll
    for (int o = 16; o; o >>= 1) {
        m0=fmaxf(m0,__shfl_xor_sync(0xffffffffu,m0,o));
        m1=fmaxf(m1,__shfl_xor_sync(0xffffffffu,m1,o));
        m2=fmaxf(m2,__shfl_xor_sync(0xffffffffu,m2,o));
        m3=fmaxf(m3,__shfl_xor_sync(0xffffffffu,m3,o));
    }
    float e0=expf(s0-m0), e1=expf(s1-m1), e2=expf(s2-m2), e3=expf(s3-m3);
    float z0=e0,z1=e1,z2=e2,z3=e3;
#pragma unroll
    for (int o = 16; o; o >>= 1) {
        z0+=__shfl_xor_sync(0xffffffffu,z0,o); z1+=__shfl_xor_sync(0xffffffffu,z1,o);
        z2+=__shfl_xor_sync(0xffffffffu,z2,o); z3+=__shfl_xor_sync(0xffffffffu,z3,o);
    }
    const float p0=e0/z0, p1=e1/z1, p2=e2/z2, p3=e3/z3;

    float* sT = ws;            // 32*33 floats (dead score smem)
    float* sP = ws + 1056;
    const float4* vv4 = (const float4*)(g_vt + (bn + nbr)*32);
#pragma unroll
    for (int c = 0; c < 8; c++) {
        float4 vv = vv4[c];
        sT[(4*c+0)*33 + lane] = vv.x;
        sT[(4*c+1)*33 + lane] = vv.y;
        sT[(4*c+2)*33 + lane] = vv.z;
        sT[(4*c+3)*33 + lane] = vv.w;
    }
    ((float4*)sP)[lane] = make_float4(p0, p1, p2, p3);
    __syncwarp();
    float acc = 0.f;
    const int r = lane & 3;
#pragma unroll
    for (int k = 0; k < 32; k++)
        acc += sP[k*4 + r] * sT[lane*33 + k];
    g_x[bm*32 + lane] = acc;
}

// ========== k1: score GEMM (FFMA2, 2 rows/warp) + top-K + attention ==========
__global__ __launch_bounds__(128, 2) void k1_fused(const float* __restrict__ src,
                                                   const float* __restrict__ tgt)
{
    extern __shared__ float sm[];
    float* s_src    = sm;                        // 256 floats
    float* s_scores = sm + 256;                  // 8 * 2048 (64KB)
    float* s_tile   = sm + 256 + TMRB*Ndim;      // 32 * 256 (32KB)
    const int tid = threadIdx.x, b = blockIdx.y, w = tid >> 5, lane = tid & 31;
    const int m0 = blockIdx.x * TMRB;
    const size_t bn = (size_t)b * Ndim;

    for (int i = tid; i < TMRB*32; i += 128) {
        int row = i >> 5, d = i & 31;
        s_src[i] = src[((size_t)(b*32+d))*Mdim + m0 + row];
    }
    __syncthreads();

    float rA[32], rB[32];
    {
        const float* sA = s_src + (w*2)*32;
#pragma unroll
        for (int d = 0; d < 32; d++) { rA[d] = sA[d]; rB[d] = sA[32+d]; }
    }

    float tvA[4] = {-FLT_MAX,-FLT_MAX,-FLT_MAX,-FLT_MAX};
    float tvB[4] = {-FLT_MAX,-FLT_MAX,-FLT_MAX,-FLT_MAX};
    int tiA[4] = {0x7fffffff,0x7fffffff,0x7fffffff,0x7fffffff};
    int tiB[4] = {0x7fffffff,0x7fffffff,0x7fffffff,0x7fffffff};

    float* wsA = s_scores + (w*2) * Ndim;
    float* wsB = wsA + Ndim;
    float4* wsA4 = (float4*)wsA;
    float4* wsB4 = (float4*)wsB;
    const float4* gt = (const float4*)(tgt + ((size_t)b*32)*Ndim);
    float4* tile4 = (float4*)s_tile;
    const ulonglong2* tile2 = (const ulonglong2*)s_tile;

    for (int t = 0; t < Ndim/TN; t++) {
        const int n0 = t * TN;
#pragma unroll
        for (int kk = 0; kk < 16; kk++) {
            int i = tid + kk*128;          // 2048 float4 slots
            int d = i >> 6, c = i & 63;
            tile4[i] = gt[(size_t)d*(Ndim/4) + (n0>>2) + c];
        }
        __syncthreads();

        unsigned long long aA0l=0, aA0h=0, aA1l=0, aA1h=0;
        unsigned long long aB0l=0, aB0h=0, aB1l=0, aB1h=0;
#pragma unroll
        for (int d = 0; d < 32; d++) {
            unsigned long long ra2 = pk2(rA[d]);
            unsigned long long rb2 = pk2(rB[d]);
            ulonglong2 t0 = tile2[d*64 + lane];
            ulonglong2 t1 = tile2[d*64 + 32 + lane];
            aA0l = fma2(ra2, t0.x, aA0l); aA0h = fma2(ra2, t0.y, aA0h);
            aA1l = fma2(ra2, t1.x, aA1l); aA1h = fma2(ra2, t1.y, aA1h);
            aB0l = fma2(rb2, t0.x, aB0l); aB0h = fma2(rb2, t0.y, aB0h);
            aB1l = fma2(rb2, t1.x, aB1l); aB1h = fma2(rb2, t1.y, aB1h);
        }
        float2 f0, f1;
        f0 = upk(aA0l); f1 = upk(aA0h);
        float4 vA0 = make_float4(f0.x, f0.y, f1.x, f1.y);
        f0 = upk(aA1l); f1 = upk(aA1h);
        float4 vA1 = make_float4(f0.x, f0.y, f1.x, f1.y);
        f0 = upk(aB0l); f1 = upk(aB0h);
        float4 vB0 = make_float4(f0.x, f0.y, f1.x, f1.y);
        f0 = upk(aB1l); f1 = upk(aB1h);
        float4 vB1 = make_float4(f0.x, f0.y, f1.x, f1.y);

        wsA4[t*64 + lane] = vA0; wsA4[t*64 + 32 + lane] = vA1;
        wsB4[t*64 + lane] = vB0; wsB4[t*64 + 32 + lane] = vB1;
        const int nb0 = n0 + lane*4, nb1 = n0 + 128 + lane*4;
        gins4(vA0, nb0, tvA, tiA); gins4(vA1, nb1, tvA, tiA);
        gins4(vB0, nb0, tvB, tiB); gins4(vB1, nb1, tvB, tiB);
        __syncthreads();
    }

    const int mA = m0 + w*2;
    sel_attn(wsA, wsA4, lane, tvA, tiA, (size_t)b*Mdim + mA,     bn);
    sel_attn(wsB, wsB4, lane, tvB, tiB, (size_t)b*Mdim + mA + 1, bn);
}

// ========== k2b: wm + w1 (GEMM over m) ==========
__global__ __launch_bounds__(128) void k2b_mlp(const float* __restrict__ finv, const float* __restrict__ srcf,
    const float* __restrict__ wm, const float* __restrict__ bm_,
    const float* __restrict__ w1, const float* __restrict__ b1_)
{
    __shared__ float s_wm[1024], s_w1[6144], s_bm[32], s_b1[64];
    __shared__ float s_x[32*33], s_attn[32*33];
    const int b = blockIdx.y, tid = threadIdx.x, m0 = blockIdx.x * 32;
    const int lane = tid & 31, og = tid >> 5, m = m0 + lane;

    for (int i = tid; i < 6144; i += 128) s_w1[i] = w1[i];
    for (int i = tid; i < 1024; i += 128) s_wm[i] = wm[i];
    if (tid < 64) s_b1[tid] = b1_[tid];
    if (tid < 32) s_bm[tid] = bm_[tid];
    for (int i = tid; i < 1024; i += 128) {
        int ml = i >> 5, d = i & 31;
        s_x[ml*33+d] = g_x[(((size_t)b*Mdim + m0) << 5) + i];
    }
    __syncthreads();
    float a[8];
#pragma unroll
    for (int j = 0; j < 8; j++) a[j] = s_bm[og*8+j];
#pragma unroll
    for (int i = 0; i < 32; i++) {
        float xv = s_x[lane*33+i];
#pragma unroll
        for (int j = 0; j < 8; j++) a[j] += s_wm[(og*8+j)*32+i] * xv;
    }
#pragma unroll
    for (int j = 0; j < 8; j++) {
        int o = og*8+j;
        s_attn[lane*33+o] = a[j];
        g_attn[((size_t)(b*32+o))*Mdim + m] = a[j];
    }
    __syncthreads();
    float h[16];
#pragma unroll
    for (int j = 0; j < 16; j++) h[j] = s_b1[og*16+j];
#pragma unroll
    for (int i = 0; i < 32; i++) {
        float xv = finv[((size_t)(b*32+i))*Mdim + m];
#pragma unroll
        for (int j = 0; j < 16; j++) h[j] += s_w1[(og*16+j)*96+i] * xv;
    }
#pragma unroll
    for (int i = 0; i < 32; i++) {
        float xv = srcf[((size_t)(b*32+i))*Mdim + m];
#pragma unroll
        for (int j = 0; j < 16; j++) h[j] += s_w1[(og*16+j)*96+32+i] * xv;
    }
#pragma unroll
    for (int i = 0; i < 32; i++) {
        float xv = s_attn[lane*33+i];
#pragma unroll
        for (int j = 0; j < 16; j++) h[j] += s_w1[(og*16+j)*96+64+i] * xv;
    }
#pragma unroll
    for (int j = 0; j < 16; j++)
        g_h[((size_t)(b*64 + og*16+j))*Mdim + m] = h[j];
}

// ========== k3: instance-norm stats ==========
__global__ void k3_stats()
{
    const int bc = blockIdx.x;
    const float4* row4 = (const float4*)(g_h + (size_t)bc * Mdim);
    float s = 0.f, s2 = 0.f;
    for (int i = threadIdx.x; i < Mdim/4; i += blockDim.x) {
        float4 v = row4[i];
        s  += v.x + v.y + v.z + v.w;
        s2 += v.x*v.x + v.y*v.y + v.z*v.z + v.w*v.w;
    }
    __shared__ float rs[32], rs2[32];
#pragma unroll
    for (int o = 16; o; o >>= 1) {
        s += __shfl_xor_sync(0xffffffffu, s, o);
        s2 += __shfl_xor_sync(0xffffffffu, s2, o);
    }
    if ((threadIdx.x & 31) == 0) { rs[threadIdx.x>>5] = s; rs2[threadIdx.x>>5] = s2; }
    __syncthreads();
    if (threadIdx.x == 0) {
        float S = 0, S2 = 0;
        for (int i = 0; i < (int)(blockDim.x>>5); i++) { S += rs[i]; S2 += rs2[i]; }
        float mu = S / (float)Mdim;
        float var = S2 / (float)Mdim - mu*mu;
        g_mean[bc] = mu; g_istd[bc] = rsqrtf(var + 1e-5f);
    }
}

// ========== k4: norm + relu + w2/wres (GEMM over m) ==========
__global__ __launch_bounds__(128) void k4_out(const float* __restrict__ finv, const float* __restrict__ srcf,
    const float* __restrict__ w2, const float* __restrict__ b2_,
    const float* __restrict__ wres, const float* __restrict__ bres, float* __restrict__ out)
{
    __shared__ float s_w[32*160], s_in[160*33], s_b[32];
    const int b = blockIdx.y, tid = threadIdx.x, m0 = blockIdx.x * 32;
    const int lane = tid & 31, og = tid >> 5;

    for (int i = tid; i < 5120; i += 128) {
        int o = i / 160, c = i % 160;
        s_w[i] = (c < 64) ? w2[o*64+c] : wres[o*96 + (c-64)];
    }
    if (tid < 32) s_b[tid] = b2_[tid] + bres[tid];
    for (int i = tid; i < 2048; i += 128) {
        int c = i >> 5, ml = i & 31;
        int bc = b*64 + c;
        float v = (g_h[(size_t)bc*Mdim + m0+ml] - g_mean[bc]) * g_istd[bc];
        s_in[c*33+ml] = fmaxf(v, 0.f);
    }
    for (int i = tid; i < 1024; i += 128) {
        int c = i >> 5, ml = i & 31;
        s_in[(64 +c)*33+ml] = finv[((size_t)(b*32+c))*Mdim + m0+ml];
        s_in[(96 +c)*33+ml] = srcf[((size_t)(b*32+c))*Mdim + m0+ml];
        s_in[(128+c)*33+ml] = g_attn[((size_t)(b*32+c))*Mdim + m0+ml];
    }
    __syncthreads();
    float acc[8];
#pragma unroll
    for (int j = 0; j < 8; j++) acc[j] = s_b[og*8+j];
    for (int c = 0; c < 160; c++) {
        float xv = s_in[c*33+lane];
#pragma unroll
        for (int j = 0; j < 8; j++) acc[j] += s_w[(og*8+j)*160+c] * xv;
    }
#pragma unroll
    for (int j = 0; j < 8; j++)
        out[((size_t)(b*32 + og*8+j))*Mdim + m0+lane] = acc[j];
}

// ========== k5: R_indicator via C-matrix ==========
__global__ __launch_bounds__(128) void k5_rind(const float* __restrict__ seqv, const float* __restrict__ teqv,
                                               const int* __restrict__ perms, float* __restrict__ out)
{
    __shared__ int   s_p[Gg*Gg];
    __shared__ float s_sr[Gg*8];      // [j][f]
    __shared__ float s_tk[Gg*12];     // [g][f] padded
    __shared__ float s_C[Gg*Gg];      // [j][g]
    __shared__ int s_nn;
    const int b = blockIdx.y, tid = threadIdx.x;
    for (int i = tid; i < Gg*Gg; i += 128) s_p[i] = perms[i];

    for (int rr = 0; rr < 8; rr++) {
        const int m = blockIdx.x * 8 + rr;
        __syncthreads();
        if (tid == 0) s_nn = g_nn[(size_t)b*Mdim + m];
        __syncthreads();
        const int nn = s_nn;
        for (int i = tid; i < Gg*8; i += 128) {
            int f = i / Gg, j = i % Gg;
            s_sr[j*8  + f] = seqv[(((size_t)(b*8+f))*Mdim + m )*Gg + j];
            s_tk[j*12 + f] = teqv[(((size_t)(b*8+f))*Ndim + nn)*Gg + j];
        }
        __syncthreads();
        const float4* sr4 = (const float4*)s_sr;
        for (int idx = tid; idx < Gg*Gg; idx += 128) {
            int j = idx / Gg, g = idx % Gg;
            float4 a0 = sr4[j*2], a1 = sr4[j*2+1];
            const float4* tg = (const float4*)(s_tk + g*12);
            float4 t0 = tg[0], t1 = tg[1];
            s_C[j*Gg + g] = a0.x*t0.x + a0.y*t0.y + a0.z*t0.z + a0.w*t0.w
                          + a1.x*t1.x + a1.y*t1.y + a1.z*t1.z + a1.w*t1.w;
        }
        __syncthreads();
        if (tid < Gg) {
            float acc = 0.f;
#pragma unroll 4
            for (int g = 0; g < Gg; g++)
                acc += s_C[s_p[g*Gg + tid]*Gg + g];
            out[(size_t)Bsz*32*Mdim + ((size_t)b*Gg + tid)*Mdim + m] = acc;
        }
    }
}

// ========== launch ==========
extern "C" void kernel_launch(void* const* d_in, const int* in_sizes, int n_in,
                              void* d_out, int out_size)
{
    (void)in_sizes; (void)n_in; (void)out_size;
    const float* src  = (const float*)d_in[0];
    const float* tgt  = (const float*)d_in[1];
    const float* seqv = (const float*)d_in[2];
    const float* teqv = (const float*)d_in[3];
    const float* finv = (const float*)d_in[4];
    const int*   perms = (const int*)d_in[5];
    const float* wq = (const float*)d_in[6];   const float* bq = (const float*)d_in[7];
    const float* wk = (const float*)d_in[8];   const float* bk = (const float*)d_in[9];
    const float* wv = (const float*)d_in[10];  const float* bv = (const float*)d_in[11];
    const float* wm = (const float*)d_in[12];  const float* bm = (const float*)d_in[13];
    const float* w1 = (const float*)d_in[14];  const float* b1 = (const float*)d_in[15];
    const float* w2 = (const float*)d_in[16];  const float* b2 = (const float*)d_in[17];
    const float* wres = (const float*)d_in[18]; const float* bres = (const float*)d_in[19];
    float* out = (float*)d_out;

    const int smem1 = (256 + TMRB*Ndim + 32*TN) * 4;   // 99328 B
    cudaFuncSetAttribute(k1_fused, cudaFuncAttributeMaxDynamicSharedMemorySize, smem1);

    k0_proj<<<dim3(32, 1, 2), 256>>>(src, tgt, wq, bq, wk, bk, wv, bv);  // 1
    k1_fused<<<dim3(Mdim/TMRB, Bsz), 128, smem1>>>(src, tgt);            // 2
    k2b_mlp<<<dim3(Mdim/32, Bsz), 128>>>(finv, src, wm, bm, w1, b1);     // 3
    k5_rind<<<dim3(Mdim/8, Bsz), 128>>>(seqv, teqv, perms, out);         // 4 <- profiled
    k3_stats<<<128, 256>>>();                                            // 5
    k4_out<<<dim3(Mdim/32, Bsz), 128>>>(finv, src, w2, b2, wres, bres, out);  // 6
}

// round 8
// speedup vs baseline: 1.2109x; 1.0852x over previous
#include <cuda_runtime.h>
#include <math.h>
#include <float.h>

#define Bsz 2
#define Mdim 2048
#define Ndim 2048
#define Kk 32
#define Gg 60
#define TMRB 8         // m-rows per block in k1 (4 warps x 2 rows)
#define TN 256         // n per tile in k1

__device__ int   g_nn[Bsz * Mdim];
__device__ float g_qs[Bsz * Mdim * 32];
__device__ float g_kt[Bsz * Ndim * 32];
__device__ float g_vt[Bsz * Ndim * 32];
__device__ float g_x [Bsz * Mdim * 32];
__device__ float g_attn[Bsz * 32 * Mdim];
__device__ float g_h[Bsz * 64 * Mdim];
__device__ float g_mean[Bsz * 64];
__device__ float g_istd[Bsz * 64];

__device__ __forceinline__ unsigned ordf(float f) {
    unsigned u = __float_as_uint(f);
    return (u & 0x80000000u) ? ~u : (u | 0x80000000u);
}
__device__ __forceinline__ void ins4(float v, int n, float tv[4], int ti[4]) {
    if (v > tv[3]) {
        if (v > tv[1]) {
            if (v > tv[0]) { tv[3]=tv[2];ti[3]=ti[2]; tv[2]=tv[1];ti[2]=ti[1]; tv[1]=tv[0];ti[1]=ti[0]; tv[0]=v;ti[0]=n; }
            else           { tv[3]=tv[2];ti[3]=ti[2]; tv[2]=tv[1];ti[2]=ti[1]; tv[1]=v;ti[1]=n; }
        } else if (v > tv[2]) { tv[3]=tv[2];ti[3]=ti[2]; tv[2]=v;ti[2]=n; }
        else { tv[3]=v; ti[3]=n; }
    }
}
__device__ __forceinline__ void gins4(float4 v, int nb, float tv[4], int ti[4]) {
    float mx = fmaxf(fmaxf(v.x, v.y), fmaxf(v.z, v.w));
    if (mx > tv[3]) {
        ins4(v.x, nb, tv, ti); ins4(v.y, nb+1, tv, ti);
        ins4(v.z, nb+2, tv, ti); ins4(v.w, nb+3, tv, ti);
    }
}

// ---- packed fp32x2 helpers (Blackwell) ----
__device__ __forceinline__ unsigned long long pk2(float x) {
    unsigned long long r;
    asm("mov.b64 %0, {%1, %1};" : "=l"(r) : "r"(__float_as_uint(x)));
    return r;
}
__device__ __forceinline__ unsigned long long fma2(unsigned long long a, unsigned long long b, unsigned long long c) {
    unsigned long long d;
    asm("fma.rn.f32x2 %0, %1, %2, %3;" : "=l"(d) : "l"(a), "l"(b), "l"(c));
    return d;
}
__device__ __forceinline__ float2 upk(unsigned long long v) {
    unsigned lo, hi;
    asm("mov.b64 {%0, %1}, %2;" : "=r"(lo), "=r"(hi) : "l"(v));
    return make_float2(__uint_as_float(lo), __uint_as_float(hi));
}

// ========== k0: per-point projections ==========
// dual=0: Q from src (blkoff slices grid); dual=1: K,V from tgt
__global__ __launch_bounds__(256) void k0_proj(const float* __restrict__ src, const float* __restrict__ tgt,
    const float* __restrict__ wq, const float* __restrict__ bq,
    const float* __restrict__ wk, const float* __restrict__ bk,
    const float* __restrict__ wv, const float* __restrict__ bv,
    int dual, int blkoff)
{
    __shared__ float sw1[1024], sw2[1024], sb1[32], sb2[32];
    const int tid = threadIdx.x;
    const float* in = dual ? tgt : src;
    const float* W1 = dual ? wk : wq;  const float* B1 = dual ? bk : bq;
    for (int i = tid; i < 1024; i += 256) { sw1[i] = W1[i]; if (dual) sw2[i] = wv[i]; }
    if (tid < 32) { sb1[tid] = B1[tid]; if (dual) sb2[tid] = bv[tid]; }
    __syncthreads();
    const int half = tid >> 7;
    const int p = (blockIdx.x + blkoff) * 128 + (tid & 127);
    const int b = p >> 11, pl = p & 2047;
    float* o1 = dual ? g_kt : g_qs;
    float a1[16], a2[16];
#pragma unroll
    for (int o = 0; o < 16; o++) { a1[o] = sb1[half*16+o]; a2[o] = dual ? sb2[half*16+o] : 0.f; }
#pragma unroll
    for (int i = 0; i < 32; i++) {
        float xv = in[((size_t)(b*32+i))*2048 + pl];
#pragma unroll
        for (int o = 0; o < 16; o++) {
            a1[o] += sw1[(half*16+o)*32+i] * xv;
            if (dual) a2[o] += sw2[(half*16+o)*32+i] * xv;
        }
    }
#pragma unroll
    for (int o = 0; o < 16; o++) {
        o1[(size_t)p*32 + half*16+o] = a1[o];
        if (dual) g_vt[(size_t)p*32 + half*16+o] = a2[o];
    }
}

// ========== k1: selection + fused attention for one m-row ==========
__device__ __forceinline__ void sel_attn(float* ws, float4* ws4, int lane,
                                         float tv[4], int ti[4],
                                         size_t bm, size_t bn)
{
    int nvalid = 4;
    int nbr = 0;
    for (int it = 0; it < Kk; it++) {
        unsigned bu = __reduce_max_sync(0xffffffffu, ordf(tv[0]));
        int cand = (ordf(tv[0]) == bu) ? ti[0] : 0x7fffffff;
        int bi = __reduce_min_sync(0xffffffffu, cand);
        if (lane == it) nbr = bi;
        if (it == 0 && lane == 0) g_nn[bm] = bi;
        if (ti[0] == bi) {
            ws[bi] = -FLT_MAX;
            tv[0]=tv[1];ti[0]=ti[1]; tv[1]=tv[2];ti[1]=ti[2]; tv[2]=tv[3];ti[2]=ti[3];
            tv[3] = -FLT_MAX; ti[3] = 0x7fffffff;
            if (--nvalid == 0) {
#pragma unroll 4
                for (int t = 0; t < Ndim/TN; t++) {
                    float4 v0 = ws4[t*64 + lane];
                    float4 v1 = ws4[t*64 + 32 + lane];
                    int nb0 = t*TN + lane*4, nb1 = t*TN + 128 + lane*4;
                    ins4(v0.x,nb0,tv,ti); ins4(v0.y,nb0+1,tv,ti); ins4(v0.z,nb0+2,tv,ti); ins4(v0.w,nb0+3,tv,ti);
                    ins4(v1.x,nb1,tv,ti); ins4(v1.y,nb1+1,tv,ti); ins4(v1.z,nb1+2,tv,ti); ins4(v1.w,nb1+3,tv,ti);
                }
                nvalid = 4;
            }
        }
    }

    const float4* q4  = (const float4*)(g_qs + bm*32);
    const float4* kk4 = (const float4*)(g_kt + (bn + nbr)*32);
    float s0=0,s1=0,s2=0,s3=0;
#pragma unroll
    for (int c = 0; c < 8; c++) {
        float4 qv = q4[c], kv = kk4[c];
        s0 += qv.x*kv.x; s1 += qv.y*kv.y; s2 += qv.z*kv.z; s3 += qv.w*kv.w;
    }
    const float sf = 0.35355339059327373f;   // 1/sqrt(8)
    s0*=sf; s1*=sf; s2*=sf; s3*=sf;
    float m0=s0,m1=s1,m2=s2,m3=s3;
#pragma unroll
    for (int o = 16; o; o >>= 1) {
        m0=fmaxf(m0,__shfl_xor_sync(0xffffffffu,m0,o));
        m1=fmaxf(m1,__shfl_xor_sync(0xffffffffu,m1,o));
        m2=fmaxf(m2,__shfl_xor_sync(0xffffffffu,m2,o));
        m3=fmaxf(m3,__shfl_xor_sync(0xffffffffu,m3,o));
    }
    float e0=expf(s0-m0), e1=expf(s1-m1), e2=expf(s2-m2), e3=expf(s3-m3);
    float z0=e0,z1=e1,z2=e2,z3=e3;
#pragma unroll
    for (int o = 16; o; o >>= 1) {
        z0+=__shfl_xor_sync(0xffffffffu,z0,o); z1+=__shfl_xor_sync(0xffffffffu,z1,o);
        z2+=__shfl_xor_sync(0xffffffffu,z2,o); z3+=__shfl_xor_sync(0xffffffffu,z3,o);
    }
    const float p0=e0/z0, p1=e1/z1, p2=e2/z2, p3=e3/z3;

    float* sT = ws;            // dead score smem
    float* sP = ws + 1056;
    const float4* vv4 = (const float4*)(g_vt + (bn + nbr)*32);
#pragma unroll
    for (int c = 0; c < 8; c++) {
        float4 vv = vv4[c];
        sT[(4*c+0)*33 + lane] = vv.x;
        sT[(4*c+1)*33 + lane] = vv.y;
        sT[(4*c+2)*33 + lane] = vv.z;
        sT[(4*c+3)*33 + lane] = vv.w;
    }
    ((float4*)sP)[lane] = make_float4(p0, p1, p2, p3);
    __syncwarp();
    float acc = 0.f;
    const int r = lane & 3;
#pragma unroll
    for (int k = 0; k < 32; k++)
        acc += sP[k*4 + r] * sT[lane*33 + k];
    g_x[bm*32 + lane] = acc;
}

// ========== k1: score GEMM (FFMA2, 2 rows/warp) + top-K + attention ==========
__global__ __launch_bounds__(128, 2) void k1_fused(const float* __restrict__ src,
                                                   const float* __restrict__ tgt)
{
    extern __shared__ float sm[];
    float* s_src    = sm;                        // 256 floats
    float* s_scores = sm + 256;                  // 8 * 2048
    float* s_tile   = sm + 256 + TMRB*Ndim;      // 32 * 256
    const int tid = threadIdx.x, b = blockIdx.y, w = tid >> 5, lane = tid & 31;
    const int m0 = blockIdx.x * TMRB;
    const size_t bn = (size_t)b * Ndim;

    for (int i = tid; i < TMRB*32; i += 128) {
        int row = i >> 5, d = i & 31;
        s_src[i] = src[((size_t)(b*32+d))*Mdim + m0 + row];
    }
    __syncthreads();

    float rA[32], rB[32];
    {
        const float* sA = s_src + (w*2)*32;
#pragma unroll
        for (int d = 0; d < 32; d++) { rA[d] = sA[d]; rB[d] = sA[32+d]; }
    }

    float tvA[4] = {-FLT_MAX,-FLT_MAX,-FLT_MAX,-FLT_MAX};
    float tvB[4] = {-FLT_MAX,-FLT_MAX,-FLT_MAX,-FLT_MAX};
    int tiA[4] = {0x7fffffff,0x7fffffff,0x7fffffff,0x7fffffff};
    int tiB[4] = {0x7fffffff,0x7fffffff,0x7fffffff,0x7fffffff};

    float* wsA = s_scores + (w*2) * Ndim;
    float* wsB = wsA + Ndim;
    float4* wsA4 = (float4*)wsA;
    float4* wsB4 = (float4*)wsB;
    const float4* gt = (const float4*)(tgt + ((size_t)b*32)*Ndim);
    float4* tile4 = (float4*)s_tile;
    const ulonglong2* tile2 = (const ulonglong2*)s_tile;

    for (int t = 0; t < Ndim/TN; t++) {
        const int n0 = t * TN;
#pragma unroll
        for (int kk = 0; kk < 16; kk++) {
            int i = tid + kk*128;
            int d = i >> 6, c = i & 63;
            tile4[i] = gt[(size_t)d*(Ndim/4) + (n0>>2) + c];
        }
        __syncthreads();

        unsigned long long aA0l=0, aA0h=0, aA1l=0, aA1h=0;
        unsigned long long aB0l=0, aB0h=0, aB1l=0, aB1h=0;
#pragma unroll
        for (int d = 0; d < 32; d++) {
            unsigned long long ra2 = pk2(rA[d]);
            unsigned long long rb2 = pk2(rB[d]);
            ulonglong2 t0 = tile2[d*64 + lane];
            ulonglong2 t1 = tile2[d*64 + 32 + lane];
            aA0l = fma2(ra2, t0.x, aA0l); aA0h = fma2(ra2, t0.y, aA0h);
            aA1l = fma2(ra2, t1.x, aA1l); aA1h = fma2(ra2, t1.y, aA1h);
            aB0l = fma2(rb2, t0.x, aB0l); aB0h = fma2(rb2, t0.y, aB0h);
            aB1l = fma2(rb2, t1.x, aB1l); aB1h = fma2(rb2, t1.y, aB1h);
        }
        float2 f0, f1;
        f0 = upk(aA0l); f1 = upk(aA0h);
        float4 vA0 = make_float4(f0.x, f0.y, f1.x, f1.y);
        f0 = upk(aA1l); f1 = upk(aA1h);
        float4 vA1 = make_float4(f0.x, f0.y, f1.x, f1.y);
        f0 = upk(aB0l); f1 = upk(aB0h);
        float4 vB0 = make_float4(f0.x, f0.y, f1.x, f1.y);
        f0 = upk(aB1l); f1 = upk(aB1h);
        float4 vB1 = make_float4(f0.x, f0.y, f1.x, f1.y);

        wsA4[t*64 + lane] = vA0; wsA4[t*64 + 32 + lane] = vA1;
        wsB4[t*64 + lane] = vB0; wsB4[t*64 + 32 + lane] = vB1;
        const int nb0 = n0 + lane*4, nb1 = n0 + 128 + lane*4;
        gins4(vA0, nb0, tvA, tiA); gins4(vA1, nb1, tvA, tiA);
        gins4(vB0, nb0, tvB, tiB); gins4(vB1, nb1, tvB, tiB);
        __syncthreads();
    }

    const int mA = m0 + w*2;
    sel_attn(wsA, wsA4, lane, tvA, tiA, (size_t)b*Mdim + mA,     bn);
    sel_attn(wsB, wsB4, lane, tvB, tiB, (size_t)b*Mdim + mA + 1, bn);
}

// ========== k2b: wm + w1 (GEMM over m) ==========
__global__ __launch_bounds__(128) void k2b_mlp(const float* __restrict__ finv, const float* __restrict__ srcf,
    const float* __restrict__ wm, const float* __restrict__ bm_,
    const float* __restrict__ w1, const float* __restrict__ b1_)
{
    __shared__ float s_wm[1024], s_w1[6144], s_bm[32], s_b1[64];
    __shared__ float s_x[32*33], s_attn[32*33];
    const int b = blockIdx.y, tid = threadIdx.x, m0 = blockIdx.x * 32;
    const int lane = tid & 31, og = tid >> 5, m = m0 + lane;

    for (int i = tid; i < 6144; i += 128) s_w1[i] = w1[i];
    for (int i = tid; i < 1024; i += 128) s_wm[i] = wm[i];
    if (tid < 64) s_b1[tid] = b1_[tid];
    if (tid < 32) s_bm[tid] = bm_[tid];
    for (int i = tid; i < 1024; i += 128) {
        int ml = i >> 5, d = i & 31;
        s_x[ml*33+d] = g_x[(((size_t)b*Mdim + m0) << 5) + i];
    }
    __syncthreads();
    float a[8];
#pragma unroll
    for (int j = 0; j < 8; j++) a[j] = s_bm[og*8+j];
#pragma unroll
    for (int i = 0; i < 32; i++) {
        float xv = s_x[lane*33+i];
#pragma unroll
        for (int j = 0; j < 8; j++) a[j] += s_wm[(og*8+j)*32+i] * xv;
    }
#pragma unroll
    for (int j = 0; j < 8; j++) {
        int o = og*8+j;
        s_attn[lane*33+o] = a[j];
        g_attn[((size_t)(b*32+o))*Mdim + m] = a[j];
    }
    __syncthreads();
    float h[16];
#pragma unroll
    for (int j = 0; j < 16; j++) h[j] = s_b1[og*16+j];
#pragma unroll
    for (int i = 0; i < 32; i++) {
        float xv = finv[((size_t)(b*32+i))*Mdim + m];
#pragma unroll
        for (int j = 0; j < 16; j++) h[j] += s_w1[(og*16+j)*96+i] * xv;
    }
#pragma unroll
    for (int i = 0; i < 32; i++) {
        float xv = srcf[((size_t)(b*32+i))*Mdim + m];
#pragma unroll
        for (int j = 0; j < 16; j++) h[j] += s_w1[(og*16+j)*96+32+i] * xv;
    }
#pragma unroll
    for (int i = 0; i < 32; i++) {
        float xv = s_attn[lane*33+i];
#pragma unroll
        for (int j = 0; j < 16; j++) h[j] += s_w1[(og*16+j)*96+64+i] * xv;
    }
#pragma unroll
    for (int j = 0; j < 16; j++)
        g_h[((size_t)(b*64 + og*16+j))*Mdim + m] = h[j];
}

// ========== k3: instance-norm stats ==========
__global__ void k3_stats()
{
    const int bc = blockIdx.x;
    const float4* row4 = (const float4*)(g_h + (size_t)bc * Mdim);
    float s = 0.f, s2 = 0.f;
    for (int i = threadIdx.x; i < Mdim/4; i += blockDim.x) {
        float4 v = row4[i];
        s  += v.x + v.y + v.z + v.w;
        s2 += v.x*v.x + v.y*v.y + v.z*v.z + v.w*v.w;
    }
    __shared__ float rs[32], rs2[32];
#pragma unroll
    for (int o = 16; o; o >>= 1) {
        s += __shfl_xor_sync(0xffffffffu, s, o);
        s2 += __shfl_xor_sync(0xffffffffu, s2, o);
    }
    if ((threadIdx.x & 31) == 0) { rs[threadIdx.x>>5] = s; rs2[threadIdx.x>>5] = s2; }
    __syncthreads();
    if (threadIdx.x == 0) {
        float S = 0, S2 = 0;
        for (int i = 0; i < (int)(blockDim.x>>5); i++) { S += rs[i]; S2 += rs2[i]; }
        float mu = S / (float)Mdim;
        float var = S2 / (float)Mdim - mu*mu;
        g_mean[bc] = mu; g_istd[bc] = rsqrtf(var + 1e-5f);
    }
}

// ========== k4: norm + relu + w2/wres (GEMM over m) ==========
__global__ __launch_bounds__(128) void k4_out(const float* __restrict__ finv, const float* __restrict__ srcf,
    const float* __restrict__ w2, const float* __restrict__ b2_,
    const float* __restrict__ wres, const float* __restrict__ bres, float* __restrict__ out)
{
    __shared__ float s_w[32*160], s_in[160*33], s_b[32];
    const int b = blockIdx.y, tid = threadIdx.x, m0 = blockIdx.x * 32;
    const int lane = tid & 31, og = tid >> 5;

    for (int i = tid; i < 5120; i += 128) {
        int o = i / 160, c = i % 160;
        s_w[i] = (c < 64) ? w2[o*64+c] : wres[o*96 + (c-64)];
    }
    if (tid < 32) s_b[tid] = b2_[tid] + bres[tid];
    for (int i = tid; i < 2048; i += 128) {
        int c = i >> 5, ml = i & 31;
        int bc = b*64 + c;
        float v = (g_h[(size_t)bc*Mdim + m0+ml] - g_mean[bc]) * g_istd[bc];
        s_in[c*33+ml] = fmaxf(v, 0.f);
    }
    for (int i = tid; i < 1024; i += 128) {
        int c = i >> 5, ml = i & 31;
        s_in[(64 +c)*33+ml] = finv[((size_t)(b*32+c))*Mdim + m0+ml];
        s_in[(96 +c)*33+ml] = srcf[((size_t)(b*32+c))*Mdim + m0+ml];
        s_in[(128+c)*33+ml] = g_attn[((size_t)(b*32+c))*Mdim + m0+ml];
    }
    __syncthreads();
    float acc[8];
#pragma unroll
    for (int j = 0; j < 8; j++) acc[j] = s_b[og*8+j];
    for (int c = 0; c < 160; c++) {
        float xv = s_in[c*33+lane];
#pragma unroll
        for (int j = 0; j < 8; j++) acc[j] += s_w[(og*8+j)*160+c] * xv;
    }
#pragma unroll
    for (int j = 0; j < 8; j++)
        out[((size_t)(b*32 + og*8+j))*Mdim + m0+lane] = acc[j];
}

// ========== k5: R_indicator — register-tiled C, conflict-free layouts ==========
__global__ __launch_bounds__(128) void k5_rind(const float* __restrict__ seqv, const float* __restrict__ teqv,
                                               const int* __restrict__ perms, float* __restrict__ out)
{
    __shared__ int   s_p[Gg*Gg];       // 14.4 KB
    __shared__ float s_sr[Gg*9];       // [j][f] stride 9 -> conflict-free store, broadcast read
    __shared__ float s_tk[8*64];       // [f][g] stride 64 -> coalesced
    __shared__ float s_C[Gg*65];       // [j][g] stride 65 -> gather banks (j+g)%32
    __shared__ float s_red[64];
    __shared__ int s_nn;
    const int b = blockIdx.y, tid = threadIdx.x;
    const int w = tid >> 5, lane = tid & 31;
    for (int i = tid; i < Gg*Gg; i += 128) s_p[i] = perms[i];

    for (int rr = 0; rr < 8; rr++) {
        const int m = blockIdx.x * 8 + rr;
        __syncthreads();
        if (tid == 0) s_nn = g_nn[(size_t)b*Mdim + m];
        __syncthreads();
        const int nn = s_nn;
        for (int i = tid; i < Gg*8; i += 128) {
            int f = i / Gg, j = i % Gg;
            s_sr[j*9 + f]  = seqv[(((size_t)(b*8+f))*Mdim + m )*Gg + j];
            s_tk[f*64 + j] = teqv[(((size_t)(b*8+f))*Ndim + nn)*Gg + j];
        }
        __syncthreads();

        // C build: warp w owns j in [w*15, w*15+15); lane owns g=lane and g=lane+32
        float rtk0[8], rtk1[8];
        const bool g1ok = (lane < Gg - 32);
#pragma unroll
        for (int f = 0; f < 8; f++) {
            rtk0[f] = s_tk[f*64 + lane];
            rtk1[f] = g1ok ? s_tk[f*64 + 32 + lane] : 0.f;
        }
#pragma unroll
        for (int jj = 0; jj < 15; jj++) {
            const int j = w*15 + jj;
            float a0 = 0.f, a1 = 0.f;
#pragma unroll
            for (int f = 0; f < 8; f++) {
                float sv = s_sr[j*9 + f];
                a0 += sv * rtk0[f];
                a1 += sv * rtk1[f];
            }
            s_C[j*65 + lane] = a0;
            if (g1ok) s_C[j*65 + 32 + lane] = a1;
        }
        __syncthreads();

        // gather: h = tid&63, half = tid>>6 covers g in [half*30, half*30+30)
        const int h = tid & 63, halfg = tid >> 6;
        float acc = 0.f;
        if (h < Gg) {
            const int gbeg = halfg * 30;
#pragma unroll 6
            for (int g = gbeg; g < gbeg + 30; g++)
                acc += s_C[s_p[g*Gg + h]*65 + g];
        }
        if (halfg == 1) s_red[h] = acc;
        __syncthreads();
        if (halfg == 0 && h < Gg)
            out[(size_t)Bsz*32*Mdim + ((size_t)b*Gg + h)*Mdim + m] = acc + s_red[h];
    }
}

// ========== launch ==========
extern "C" void kernel_launch(void* const* d_in, const int* in_sizes, int n_in,
                              void* d_out, int out_size)
{
    (void)in_sizes; (void)n_in; (void)out_size;
    const float* src  = (const float*)d_in[0];
    const float* tgt  = (const float*)d_in[1];
    const float* seqv = (const float*)d_in[2];
    const float* teqv = (const float*)d_in[3];
    const float* finv = (const float*)d_in[4];
    const int*   perms = (const int*)d_in[5];
    const float* wq = (const float*)d_in[6];   const float* bq = (const float*)d_in[7];
    const float* wk = (const float*)d_in[8];   const float* bk = (const float*)d_in[9];
    const float* wv = (const float*)d_in[10];  const float* bv = (const float*)d_in[11];
    const float* wm = (const float*)d_in[12];  const float* bm = (const float*)d_in[13];
    const float* w1 = (const float*)d_in[14];  const float* b1 = (const float*)d_in[15];
    const float* w2 = (const float*)d_in[16];  const float* b2 = (const float*)d_in[17];
    const float* wres = (const float*)d_in[18]; const float* bres = (const float*)d_in[19];
    float* out = (float*)d_out;

    const int smem1 = (256 + TMRB*Ndim + 32*TN) * 4;   // 99328 B
    cudaFuncSetAttribute(k1_fused, cudaFuncAttributeMaxDynamicSharedMemorySize, smem1);

    k0_proj<<<16, 256>>>(src, tgt, wq, bq, wk, bk, wv, bv, 0, 0);    // 1: Q half
    k0_proj<<<16, 256>>>(src, tgt, wq, bq, wk, bk, wv, bv, 0, 16);   // 2: Q half
    k0_proj<<<32, 256>>>(src, tgt, wq, bq, wk, bk, wv, bv, 1, 0);    // 3: K,V
    k1_fused<<<dim3(Mdim/TMRB, Bsz), 128, smem1>>>(src, tgt);        // 4 <- profiled
    k2b_mlp<<<dim3(Mdim/32, Bsz), 128>>>(finv, src, wm, bm, w1, b1);
    k5_rind<<<dim3(Mdim/8, Bsz), 128>>>(seqv, teqv, perms, out);
    k3_stats<<<128, 256>>>();
    k4_out<<<dim3(Mdim/32, Bsz), 128>>>(finv, src, w2, b2, wres, bres, out);
}